// round 8
// baseline (speedup 1.0000x reference)
#include <cuda_runtime.h>
#include <cstdint>

// Fixed dims: B=4, S=2048 -> M=8192, H=2048, I=8192
#define M_TOK 8192
#define H_DIM 2048
#define I_DIM 8192
#define LN_EPS 1e-6f

// ---------------- scratch (device globals; no allocs) ----------------------
__device__ float g_Y  [(size_t)M_TOK * H_DIM];       //  67 MB LN out (tf32, k-perm)
__device__ float g_W1T[(size_t)2 * I_DIM * H_DIM];   // 134 MB W1^T [16384,2048] (k-perm)
__device__ float g_W2T[(size_t)H_DIM * I_DIM];       //  67 MB W2^T [2048,8192]  (k-perm)
__device__ float g_Z  [(size_t)M_TOK * I_DIM];       // 268 MB GeGLU out (tf32, k-perm)

// ---------------- helpers --------------------------------------------------
__device__ __forceinline__ float to_tf32(float x) {
    uint32_t u; asm("cvt.rna.tf32.f32 %0, %1;" : "=r"(u) : "f"(x));
    return __uint_as_float(u);
}
__device__ __forceinline__ float gelu_tanh(float v) {
    float u = 0.7978845608028654f * (v + 0.044715f * v * v * v);
    return 0.5f * v * (1.0f + tanhf(u));
}
// k-permutation within a 32-block: both GEMM operands share it -> result unchanged.
__device__ __forceinline__ int jmap(int k) {          // k in [0,32)
    return 8 * (k & 3) + 2 * (k >> 3) + ((k >> 2) & 1);
}
__device__ __forceinline__ void cp_async16(void* s, const void* g) {
    unsigned a = (unsigned)__cvta_generic_to_shared(s);
    asm volatile("cp.async.cg.shared.global [%0], [%1], 16;\n" :: "r"(a), "l"(g) : "memory");
}
__device__ __forceinline__ void cp_commit() {
    asm volatile("cp.async.commit_group;\n" ::: "memory");
}
__device__ __forceinline__ void mma_tf32(float c[4], uint32_t a0, uint32_t a1,
                                         uint32_t a2, uint32_t a3,
                                         uint32_t b0, uint32_t b1) {
    asm volatile(
        "mma.sync.aligned.m16n8k8.row.col.f32.tf32.tf32.f32 "
        "{%0,%1,%2,%3}, {%4,%5,%6,%7}, {%8,%9}, {%0,%1,%2,%3};\n"
        : "+f"(c[0]), "+f"(c[1]), "+f"(c[2]), "+f"(c[3])
        : "r"(a0), "r"(a1), "r"(a2), "r"(a3), "r"(b0), "r"(b1));
}

// ---------------- 1) LayerNorm -> Y (tf32, k-permuted cols) ---------------
__global__ void __launch_bounds__(256)
ln_kernel(const float* __restrict__ x, const float* __restrict__ gamma,
          const float* __restrict__ beta, float* __restrict__ y)
{
    __shared__ float red1[8], red2[8];
    const int row = blockIdx.x, t = threadIdx.x;
    const int lane = t & 31, w = t >> 5;

    const float4* xr = (const float4*)(x + (size_t)row * H_DIM);
    float4 v0 = xr[t], v1 = xr[t + 256];
    float s = v0.x + v0.y + v0.z + v0.w + v1.x + v1.y + v1.z + v1.w;
    #pragma unroll
    for (int o = 16; o > 0; o >>= 1) s += __shfl_xor_sync(0xffffffffu, s, o);
    if (lane == 0) red1[w] = s;
    __syncthreads();
    float tot = 0.f;
    #pragma unroll
    for (int i = 0; i < 8; i++) tot += red1[i];
    const float mu = tot * (1.0f / H_DIM);

    float d[8] = {v0.x - mu, v0.y - mu, v0.z - mu, v0.w - mu,
                  v1.x - mu, v1.y - mu, v1.z - mu, v1.w - mu};
    float ss = 0.f;
    #pragma unroll
    for (int i = 0; i < 8; i++) ss += d[i] * d[i];
    #pragma unroll
    for (int o = 16; o > 0; o >>= 1) ss += __shfl_xor_sync(0xffffffffu, ss, o);
    if (lane == 0) red2[w] = ss;
    __syncthreads();
    float tot2 = 0.f;
    #pragma unroll
    for (int i = 0; i < 8; i++) tot2 += red2[i];
    const float rstd = rsqrtf(tot2 * (1.0f / H_DIM) + LN_EPS);

    const float4* g4 = (const float4*)gamma;
    const float4* b4 = (const float4*)beta;
    float* yr = y + (size_t)row * H_DIM;

    #pragma unroll
    for (int half = 0; half < 2; half++) {
        const int tt = t + half * 256;
        float4 ga = g4[tt], ba = b4[tt];
        const float* dd = d + half * 4;
        float o0 = to_tf32(dd[0] * rstd * ga.x + ba.x);
        float o1 = to_tf32(dd[1] * rstd * ga.y + ba.y);
        float o2 = to_tf32(dd[2] * rstd * ga.z + ba.z);
        float o3 = to_tf32(dd[3] * rstd * ga.w + ba.w);
        const int k0   = 4 * tt;
        const int base = k0 & ~31;
        const int off  = 2 * ((tt & 7) >> 1) + (tt & 1);
        yr[base + 0  + off] = o0;     // j = 8*d + off
        yr[base + 8  + off] = o1;
        yr[base + 16 + off] = o2;
        yr[base + 24 + off] = o3;
    }
}

// ---------------- 2) transpose + tf32 + k-perm: out[c][perm(r)] ------------
__global__ void __launch_bounds__(256)
transpose_tf32(const float* __restrict__ in, float* __restrict__ out, int R, int C)
{
    __shared__ float t[32][33];
    const int bx = blockIdx.x * 32, by = blockIdx.y * 32;
    const int tx = threadIdx.x & 31, ty = threadIdx.x >> 5;
    #pragma unroll
    for (int j = 0; j < 4; j++)
        t[ty + j * 8][tx] = in[(size_t)(by + ty + j * 8) * C + bx + tx];
    __syncthreads();
    const int pc = by + jmap(tx);     // permuted k-col (by is 32-aligned)
    #pragma unroll
    for (int j = 0; j < 4; j++)
        out[(size_t)(bx + ty + j * 8) * R + pc] = to_tf32(t[tx][ty + j * 8]);
}

// ---------------- 3) mma.sync tf32 GEMM, vectorized frags ------------------
// A [M,K] row-major k-perm; Bt [N,K] row-major k-perm. CTA 128 x (G?64:128),
// BK=32, 8 warps (4m x 2n), double-buffered cp.async.
// G=1: B rows = 64 gelu-branch + 64 linear-branch; epilogue writes
//      Z = tf32(gelu(Dg)*Dl) with k-permuted columns (Z feeds GEMM2).
#define BK 32
#define ASTR 36
#define TBUF (128 * ASTR)                      // floats per tile buffer
#define GEMM_SMEM (4 * TBUF * 4)               // 73728 B

template<int G>
__global__ void __launch_bounds__(256, 2)
gemm_mma(const float* __restrict__ A, const float* __restrict__ Bt,
         float* __restrict__ C, int K, int ldc)
{
    extern __shared__ float sm[];
    float* As = sm;
    float* Bs = sm + 2 * TBUF;

    const int tid  = threadIdx.x;
    const int lane = tid & 31, wid = tid >> 5;
    const int q = lane >> 2, c = lane & 3;
    const int wm = wid & 3, wn = wid >> 2;

    // m-supertile swizzle (groups of 8 m-tiles) for B-slab L2 reuse
    const int lin  = blockIdx.y * gridDim.x + blockIdx.x;
    const int mt_  = (lin / (8 * gridDim.x)) * 8 + (lin % 8);
    const int nt_  = (lin % (8 * gridDim.x)) / 8;
    const int m0   = mt_ * 128;
    const int n0   = nt_ * (G ? 64 : 128);

    float acc[2][8][4];
    #pragma unroll
    for (int i = 0; i < 2; i++)
        #pragma unroll
        for (int j = 0; j < 8; j++)
            #pragma unroll
            for (int p = 0; p < 4; p++) acc[i][j][p] = 0.f;

    const int NK = K >> 5;

    auto load_tiles = [&](int buf, int kt) {
        float* as = As + buf * TBUF;
        float* bs = Bs + buf * TBUF;
        const float* Ag = A  + (size_t)m0 * K + kt * BK;
        #pragma unroll
        for (int i = 0; i < 4; i++) {
            const int idx = tid + i * 256;
            const int r = idx >> 3, cc = (idx & 7) << 2;
            cp_async16(as + r * ASTR + cc, Ag + (size_t)r * K + cc);
            int brow;
            if (G) brow = (r < 64) ? (n0 + r) : (I_DIM + n0 + r - 64);
            else   brow = n0 + r;
            cp_async16(bs + r * ASTR + cc, Bt + (size_t)brow * K + kt * BK + cc);
        }
    };

    load_tiles(0, 0);
    cp_commit();

    for (int kt = 0; kt < NK; ++kt) {
        if (kt + 1 < NK) load_tiles((kt + 1) & 1, kt + 1);
        cp_commit();
        asm volatile("cp.async.wait_group 1;\n" ::: "memory");
        __syncthreads();

        const float* as = As + (kt & 1) * TBUF;
        const float* bs = Bs + (kt & 1) * TBUF;

        #pragma unroll
        for (int s2 = 0; s2 < 2; ++s2) {              // halves: k-steps {0,1},{2,3}
            float4 a4[2][2];
            #pragma unroll
            for (int mt = 0; mt < 2; ++mt)
                #pragma unroll
                for (int r8 = 0; r8 < 2; ++r8)
                    a4[mt][r8] = *(const float4*)(as + (wm * 32 + mt * 16 + r8 * 8 + q) * ASTR
                                                  + c * 8 + s2 * 4);
            #pragma unroll
            for (int ug = 0; ug < 2; ++ug) {          // B in chunks of 4 slots
                float4 b4[4];
                #pragma unroll
                for (int j = 0; j < 4; ++j) {
                    const int u = ug * 4 + j;
                    int brow;
                    if (G) brow = (u >> 2) * 64 + wn * 32 + (u & 3) * 8 + q;
                    else   brow = wn * 64 + u * 8 + q;
                    b4[j] = *(const float4*)(bs + brow * ASTR + c * 8 + s2 * 4);
                }
                #pragma unroll
                for (int mt = 0; mt < 2; ++mt)
                    #pragma unroll
                    for (int j = 0; j < 4; ++j) {
                        const int u = ug * 4 + j;
                        mma_tf32(acc[mt][u],
                                 __float_as_uint(a4[mt][0].x), __float_as_uint(a4[mt][1].x),
                                 __float_as_uint(a4[mt][0].y), __float_as_uint(a4[mt][1].y),
                                 __float_as_uint(b4[j].x),     __float_as_uint(b4[j].y));
                        mma_tf32(acc[mt][u],
                                 __float_as_uint(a4[mt][0].z), __float_as_uint(a4[mt][1].z),
                                 __float_as_uint(a4[mt][0].w), __float_as_uint(a4[mt][1].w),
                                 __float_as_uint(b4[j].z),     __float_as_uint(b4[j].w));
                    }
            }
        }
        __syncthreads();
    }

    if (G) {
        // GeGLU epilogue: slots 0..3 = gelu branch, 4..7 = linear branch.
        // Z columns are k-permuted (they are GEMM2's K dimension).
        #pragma unroll
        for (int mt = 0; mt < 2; ++mt)
            #pragma unroll
            for (int nt = 0; nt < 4; ++nt)
                #pragma unroll
                for (int rr = 0; rr < 2; ++rr) {
                    const int row  = m0 + wm * 32 + mt * 16 + rr * 8 + q;
                    const int ic0  = n0 + wn * 32 + nt * 8 + 2 * c;
                    const float z0 = to_tf32(gelu_tanh(acc[mt][nt][rr * 2 + 0]) *
                                             acc[mt][4 + nt][rr * 2 + 0]);
                    const float z1 = to_tf32(gelu_tanh(acc[mt][nt][rr * 2 + 1]) *
                                             acc[mt][4 + nt][rr * 2 + 1]);
                    float* zr = C + (size_t)row * ldc;
                    zr[(ic0       & ~31) + jmap(ic0       & 31)] = z0;
                    zr[((ic0 + 1) & ~31) + jmap((ic0 + 1) & 31)] = z1;
                }
    } else {
        #pragma unroll
        for (int mt = 0; mt < 2; ++mt) {
            const int r = m0 + wm * 32 + mt * 16 + q;
            #pragma unroll
            for (int u = 0; u < 8; ++u) {
                const int cc = n0 + wn * 64 + u * 8 + 2 * c;
                *(float2*)(C + (size_t)r * ldc + cc)       = make_float2(acc[mt][u][0], acc[mt][u][1]);
                *(float2*)(C + (size_t)(r + 8) * ldc + cc) = make_float2(acc[mt][u][2], acc[mt][u][3]);
            }
        }
    }
}

// ---------------- launch ---------------------------------------------------
extern "C" void kernel_launch(void* const* d_in, const int* in_sizes, int n_in,
                              void* d_out, int out_size)
{
    (void)in_sizes; (void)n_in; (void)out_size;
    const float* x     = (const float*)d_in[0];
    const float* gamma = (const float*)d_in[1];
    const float* beta  = (const float*)d_in[2];
    const float* k1    = (const float*)d_in[3];
    const float* k2    = (const float*)d_in[4];
    float* out = (float*)d_out;

    float *Y, *W1T, *W2T, *Z;
    cudaGetSymbolAddress((void**)&Y,   g_Y);
    cudaGetSymbolAddress((void**)&W1T, g_W1T);
    cudaGetSymbolAddress((void**)&W2T, g_W2T);
    cudaGetSymbolAddress((void**)&Z,   g_Z);

    cudaFuncSetAttribute(gemm_mma<1>, cudaFuncAttributeMaxDynamicSharedMemorySize, GEMM_SMEM);
    cudaFuncSetAttribute(gemm_mma<0>, cudaFuncAttributeMaxDynamicSharedMemorySize, GEMM_SMEM);

    // 1) LayerNorm -> Y (tf32, k-perm)
    ln_kernel<<<M_TOK, 256>>>(x, gamma, beta, Y);

    // 2) W1 [2048,16384] -> W1T [16384,2048];  W2 [8192,2048] -> W2T [2048,8192]
    transpose_tf32<<<dim3(16384 / 32, 2048 / 32), 256>>>(k1, W1T, 2048, 16384);
    transpose_tf32<<<dim3(2048 / 32, 8192 / 32), 256>>>(k2, W2T, 8192, 2048);

    // 3) GEMM1 + fused GeGLU -> Z   (n-tiles = I/64 = 128, m-tiles = 64)
    gemm_mma<1><<<dim3(I_DIM / 64, M_TOK / 128), 256, GEMM_SMEM>>>(Y, W1T, Z, H_DIM, I_DIM);

    // 4) GEMM2 -> out              (n-tiles = H/128 = 16, m-tiles = 64)
    gemm_mma<0><<<dim3(H_DIM / 128, M_TOK / 128), 256, GEMM_SMEM>>>(Z, W2T, out, I_DIM, H_DIM);
}

// round 9
// speedup vs baseline: 1.2342x; 1.2342x over previous
#include <cuda_runtime.h>
#include <cstdint>

// Fixed dims: B=4, S=2048 -> M=8192, H=2048, I=8192
#define M_TOK 8192
#define H_DIM 2048
#define I_DIM 8192
#define LN_EPS 1e-6f

// ---------------- scratch (device globals; no allocs) ----------------------
__device__ float g_Y  [(size_t)M_TOK * H_DIM];       //  67 MB LN out (tf32, k-perm)
__device__ float g_W1T[(size_t)2 * I_DIM * H_DIM];   // 134 MB W1^T [16384,2048] (k-perm)
__device__ float g_W2T[(size_t)H_DIM * I_DIM];       //  67 MB W2^T [2048,8192]  (k-perm)
__device__ float g_Z  [(size_t)M_TOK * I_DIM];       // 268 MB GeGLU out (tf32, k-perm)

// ---------------- helpers --------------------------------------------------
__device__ __forceinline__ float to_tf32(float x) {
    uint32_t u; asm("cvt.rna.tf32.f32 %0, %1;" : "=r"(u) : "f"(x));
    return __uint_as_float(u);
}
__device__ __forceinline__ float gelu_tanh(float v) {
    float u = 0.7978845608028654f * (v + 0.044715f * v * v * v);
    return 0.5f * v * (1.0f + tanhf(u));
}
// k-permutation within a 32-block; applied to BOTH operands -> result invariant.
__device__ __forceinline__ int jmap(int k) {          // k in [0,32)
    return 8 * (k & 3) + 2 * (k >> 3) + ((k >> 2) & 1);
}
__device__ __forceinline__ void cp_async16(void* s, const void* g) {
    unsigned a = (unsigned)__cvta_generic_to_shared(s);
    asm volatile("cp.async.cg.shared.global [%0], [%1], 16;\n" :: "r"(a), "l"(g) : "memory");
}
__device__ __forceinline__ void cp_commit() {
    asm volatile("cp.async.commit_group;\n" ::: "memory");
}
__device__ __forceinline__ void mma_tf32(float c[4], uint32_t a0, uint32_t a1,
                                         uint32_t a2, uint32_t a3,
                                         uint32_t b0, uint32_t b1) {
    asm volatile(
        "mma.sync.aligned.m16n8k8.row.col.f32.tf32.tf32.f32 "
        "{%0,%1,%2,%3}, {%4,%5,%6,%7}, {%8,%9}, {%0,%1,%2,%3};\n"
        : "+f"(c[0]), "+f"(c[1]), "+f"(c[2]), "+f"(c[3])
        : "r"(a0), "r"(a1), "r"(a2), "r"(a3), "r"(b0), "r"(b1));
}

// ---------------- 1) LayerNorm -> Y (tf32, k-permuted cols) ---------------
__global__ void __launch_bounds__(256)
ln_kernel(const float* __restrict__ x, const float* __restrict__ gamma,
          const float* __restrict__ beta, float* __restrict__ y)
{
    __shared__ float red1[8], red2[8];
    const int row = blockIdx.x, t = threadIdx.x;
    const int lane = t & 31, w = t >> 5;

    const float4* xr = (const float4*)(x + (size_t)row * H_DIM);
    float4 v0 = xr[t], v1 = xr[t + 256];
    float s = v0.x + v0.y + v0.z + v0.w + v1.x + v1.y + v1.z + v1.w;
    #pragma unroll
    for (int o = 16; o > 0; o >>= 1) s += __shfl_xor_sync(0xffffffffu, s, o);
    if (lane == 0) red1[w] = s;
    __syncthreads();
    float tot = 0.f;
    #pragma unroll
    for (int i = 0; i < 8; i++) tot += red1[i];
    const float mu = tot * (1.0f / H_DIM);

    float d[8] = {v0.x - mu, v0.y - mu, v0.z - mu, v0.w - mu,
                  v1.x - mu, v1.y - mu, v1.z - mu, v1.w - mu};
    float ss = 0.f;
    #pragma unroll
    for (int i = 0; i < 8; i++) ss += d[i] * d[i];
    #pragma unroll
    for (int o = 16; o > 0; o >>= 1) ss += __shfl_xor_sync(0xffffffffu, ss, o);
    if (lane == 0) red2[w] = ss;
    __syncthreads();
    float tot2 = 0.f;
    #pragma unroll
    for (int i = 0; i < 8; i++) tot2 += red2[i];
    const float rstd = rsqrtf(tot2 * (1.0f / H_DIM) + LN_EPS);

    const float4* g4 = (const float4*)gamma;
    const float4* b4 = (const float4*)beta;
    float* yr = y + (size_t)row * H_DIM;

    #pragma unroll
    for (int half = 0; half < 2; half++) {
        const int tt = t + half * 256;
        float4 ga = g4[tt], ba = b4[tt];
        const float* dd = d + half * 4;
        float o0 = to_tf32(dd[0] * rstd * ga.x + ba.x);
        float o1 = to_tf32(dd[1] * rstd * ga.y + ba.y);
        float o2 = to_tf32(dd[2] * rstd * ga.z + ba.z);
        float o3 = to_tf32(dd[3] * rstd * ga.w + ba.w);
        const int k0   = 4 * tt;
        const int base = k0 & ~31;
        const int off  = 2 * ((tt & 7) >> 1) + (tt & 1);
        yr[base + 0  + off] = o0;     // j = 8*d + off  (jmap of k0..k0+3)
        yr[base + 8  + off] = o1;
        yr[base + 16 + off] = o2;
        yr[base + 24 + off] = o3;
    }
}

// ---------------- 2) transpose + tf32 + k-perm: out[c][perm(r)] ------------
__global__ void __launch_bounds__(256)
transpose_tf32(const float* __restrict__ in, float* __restrict__ out, int R, int C)
{
    __shared__ float t[32][33];
    const int bx = blockIdx.x * 32, by = blockIdx.y * 32;
    const int tx = threadIdx.x & 31, ty = threadIdx.x >> 5;
    #pragma unroll
    for (int j = 0; j < 4; j++)
        t[ty + j * 8][tx] = in[(size_t)(by + ty + j * 8) * C + bx + tx];
    __syncthreads();
    const int pc = by + jmap(tx);     // permuted k-col (by is 32-aligned)
    #pragma unroll
    for (int j = 0; j < 4; j++)
        out[(size_t)(bx + ty + j * 8) * R + pc] = to_tf32(t[tx][ty + j * 8]);
}

// ---------------- 3) mma.sync tf32 GEMM, XOR-swizzled smem -----------------
// A [M,K] row-major k-perm; Bt [N,K] row-major k-perm. CTA 128 rows x 128
// B-rows, BK=32, 8 warps (4m x 2n), double-buffered cp.async.
// Smem tile: 128 rows x 32 floats (128B); 16B unit u at byte row*128 + (u^(row&7))*16.
// G=1: B rows = 64 gelu-branch + 64 linear-branch; epilogue writes
//      Z = tf32(gelu(Dg)*Dl), k-permuted columns (Z feeds GEMM2's K dim).
#define BK 32
#define TBUF (128 * 32)                        // floats per tile buffer
#define GEMM_SMEM (4 * TBUF * 4)               // 65536 B

template<int G>
__global__ void __launch_bounds__(256, 2)
gemm_mma(const float* __restrict__ A, const float* __restrict__ Bt,
         float* __restrict__ C, int K, int ldc)
{
    extern __shared__ float sm[];
    float* As = sm;
    float* Bs = sm + 2 * TBUF;

    const int tid  = threadIdx.x;
    const int lane = tid & 31, wid = tid >> 5;
    const int q = lane >> 2, c = lane & 3;
    const int wm = wid & 3, wn = wid >> 2;

    // m-supertile swizzle (groups of 8 m-tiles) for B-slab L2 reuse
    const int lin  = blockIdx.y * gridDim.x + blockIdx.x;
    const int mt_  = (lin / (8 * gridDim.x)) * 8 + (lin % 8);
    const int nt_  = (lin % (8 * gridDim.x)) / 8;
    const int m0   = mt_ * 128;
    const int n0   = nt_ * (G ? 64 : 128);

    float acc[2][8][4];
    #pragma unroll
    for (int i = 0; i < 2; i++)
        #pragma unroll
        for (int j = 0; j < 8; j++)
            #pragma unroll
            for (int p = 0; p < 4; p++) acc[i][j][p] = 0.f;

    const int NK = K >> 5;

    // cp.async: thread writes row = idx>>3, 16B-unit u = idx&7, swizzled u^(row&7)
    auto load_tiles = [&](int buf, int kt) {
        float* as = As + buf * TBUF;
        float* bs = Bs + buf * TBUF;
        const float* Ag = A + (size_t)m0 * K + kt * BK;
        #pragma unroll
        for (int i = 0; i < 4; i++) {
            const int idx = tid + i * 256;
            const int r = idx >> 3, u = idx & 7;
            const int su = (u ^ (r & 7)) << 2;          // swizzled float offset
            cp_async16(as + r * 32 + su, Ag + (size_t)r * K + u * 4);
            int brow;
            if (G) brow = (r < 64) ? (n0 + r) : (I_DIM + n0 + r - 64);
            else   brow = n0 + r;
            cp_async16(bs + r * 32 + su, Bt + (size_t)brow * K + kt * BK + u * 4);
        }
    };

    load_tiles(0, 0);
    cp_commit();

    for (int kt = 0; kt < NK; ++kt) {
        if (kt + 1 < NK) load_tiles((kt + 1) & 1, kt + 1);
        cp_commit();
        asm volatile("cp.async.wait_group 1;\n" ::: "memory");
        __syncthreads();

        const float* as = As + (kt & 1) * TBUF;
        const float* bs = Bs + (kt & 1) * TBUF;

        #pragma unroll
        for (int s2 = 0; s2 < 2; ++s2) {              // k-halves {0,1},{2,3}
            const int fu = ((c * 2 + s2) ^ q) << 2;   // swizzled unit (row&7 == q)
            float4 a4[2][2];
            #pragma unroll
            for (int mt = 0; mt < 2; ++mt)
                #pragma unroll
                for (int r8 = 0; r8 < 2; ++r8)
                    a4[mt][r8] = *(const float4*)(as + (wm * 32 + mt * 16 + r8 * 8 + q) * 32 + fu);
            #pragma unroll
            for (int ug = 0; ug < 2; ++ug) {          // B slots in chunks of 4
                float4 b4[4];
                #pragma unroll
                for (int j = 0; j < 4; ++j) {
                    const int u = ug * 4 + j;
                    int brow;
                    if (G) brow = (u >> 2) * 64 + wn * 32 + (u & 3) * 8 + q;
                    else   brow = wn * 64 + u * 8 + q;
                    b4[j] = *(const float4*)(bs + brow * 32 + fu);
                }
                #pragma unroll
                for (int mt = 0; mt < 2; ++mt)
                    #pragma unroll
                    for (int j = 0; j < 4; ++j) {
                        const int u = ug * 4 + j;
                        mma_tf32(acc[mt][u],
                                 __float_as_uint(a4[mt][0].x), __float_as_uint(a4[mt][1].x),
                                 __float_as_uint(a4[mt][0].y), __float_as_uint(a4[mt][1].y),
                                 __float_as_uint(b4[j].x),     __float_as_uint(b4[j].y));
                        mma_tf32(acc[mt][u],
                                 __float_as_uint(a4[mt][0].z), __float_as_uint(a4[mt][1].z),
                                 __float_as_uint(a4[mt][0].w), __float_as_uint(a4[mt][1].w),
                                 __float_as_uint(b4[j].z),     __float_as_uint(b4[j].w));
                    }
            }
        }
        __syncthreads();
    }

    if (G) {
        // GeGLU epilogue: slots 0..3 = gelu branch, 4..7 = linear branch.
        // Z columns are k-permuted (they are GEMM2's K dimension).
        #pragma unroll
        for (int mt = 0; mt < 2; ++mt)
            #pragma unroll
            for (int nt = 0; nt < 4; ++nt)
                #pragma unroll
                for (int rr = 0; rr < 2; ++rr) {
                    const int row  = m0 + wm * 32 + mt * 16 + rr * 8 + q;
                    const int ic0  = n0 + wn * 32 + nt * 8 + 2 * c;
                    const float z0 = to_tf32(gelu_tanh(acc[mt][nt][rr * 2 + 0]) *
                                             acc[mt][4 + nt][rr * 2 + 0]);
                    const float z1 = to_tf32(gelu_tanh(acc[mt][nt][rr * 2 + 1]) *
                                             acc[mt][4 + nt][rr * 2 + 1]);
                    float* zr = C + (size_t)row * ldc;
                    zr[(ic0       & ~31) + jmap(ic0       & 31)] = z0;
                    zr[((ic0 + 1) & ~31) + jmap((ic0 + 1) & 31)] = z1;
                }
    } else {
        #pragma unroll
        for (int mt = 0; mt < 2; ++mt) {
            const int r = m0 + wm * 32 + mt * 16 + q;
            #pragma unroll
            for (int u = 0; u < 8; ++u) {
                const int cc = n0 + wn * 64 + u * 8 + 2 * c;
                *(float2*)(C + (size_t)r * ldc + cc)       = make_float2(acc[mt][u][0], acc[mt][u][1]);
                *(float2*)(C + (size_t)(r + 8) * ldc + cc) = make_float2(acc[mt][u][2], acc[mt][u][3]);
            }
        }
    }
}

// ---------------- launch ---------------------------------------------------
extern "C" void kernel_launch(void* const* d_in, const int* in_sizes, int n_in,
                              void* d_out, int out_size)
{
    (void)in_sizes; (void)n_in; (void)out_size;
    const float* x     = (const float*)d_in[0];
    const float* gamma = (const float*)d_in[1];
    const float* beta  = (const float*)d_in[2];
    const float* k1    = (const float*)d_in[3];
    const float* k2    = (const float*)d_in[4];
    float* out = (float*)d_out;

    float *Y, *W1T, *W2T, *Z;
    cudaGetSymbolAddress((void**)&Y,   g_Y);
    cudaGetSymbolAddress((void**)&W1T, g_W1T);
    cudaGetSymbolAddress((void**)&W2T, g_W2T);
    cudaGetSymbolAddress((void**)&Z,   g_Z);

    cudaFuncSetAttribute(gemm_mma<1>, cudaFuncAttributeMaxDynamicSharedMemorySize, GEMM_SMEM);
    cudaFuncSetAttribute(gemm_mma<0>, cudaFuncAttributeMaxDynamicSharedMemorySize, GEMM_SMEM);

    // 1) LayerNorm -> Y (tf32, k-perm)
    ln_kernel<<<M_TOK, 256>>>(x, gamma, beta, Y);

    // 2) W1 [2048,16384] -> W1T [16384,2048];  W2 [8192,2048] -> W2T [2048,8192]
    transpose_tf32<<<dim3(16384 / 32, 2048 / 32), 256>>>(k1, W1T, 2048, 16384);
    transpose_tf32<<<dim3(2048 / 32, 8192 / 32), 256>>>(k2, W2T, 8192, 2048);

    // 3) GEMM1 + fused GeGLU -> Z   (n-tiles = I/64 = 128, m-tiles = 64)
    gemm_mma<1><<<dim3(I_DIM / 64, M_TOK / 128), 256, GEMM_SMEM>>>(Y, W1T, Z, H_DIM, I_DIM);

    // 4) GEMM2 -> out              (n-tiles = H/128 = 16, m-tiles = 64)
    gemm_mma<0><<<dim3(H_DIM / 128, M_TOK / 128), 256, GEMM_SMEM>>>(Z, W2T, out, I_DIM, H_DIM);
}

// round 12
// speedup vs baseline: 2.2512x; 1.8240x over previous
#include <cuda_runtime.h>
#include <cuda_fp16.h>
#include <cstdint>

// Fixed dims: B=4, S=2048 -> M=8192, H=2048, I=8192
#define M_TOK 8192
#define H_DIM 2048
#define I_DIM 8192
#define LN_EPS 1e-6f

// ---------------- scratch (device globals; no allocs) ----------------------
__device__ __half g_Y  [(size_t)M_TOK * H_DIM];       //  33 MB LN out (fp16, k-perm)
__device__ __half g_W1T[(size_t)2 * I_DIM * H_DIM];   //  67 MB W1^T [16384,2048] (k-perm)
__device__ __half g_W2T[(size_t)H_DIM * I_DIM];       //  33 MB W2^T [2048,8192]  (k-perm)
__device__ __half g_Z  [(size_t)M_TOK * I_DIM];       // 134 MB GeGLU out (fp16, k-perm)

// ---------------- helpers --------------------------------------------------
__device__ __forceinline__ float gelu_tanh(float v) {
    float u = 0.7978845608028654f * (v + 0.044715f * v * v * v);
    return 0.5f * v * (1.0f + tanhf(u));
}
// k-permutation within a 32-block; applied to BOTH operands -> result invariant.
// p32(k) = 8*((k>>1)&3) + 4*(k>>4) + 2*((k>>3)&1) + (k&1)
__device__ __forceinline__ int p32(int k) {
    return 8 * ((k >> 1) & 3) + 4 * (k >> 4) + 2 * ((k >> 3) & 1) + (k & 1);
}
// inverse: k = 16*((p>>2)&1) + 8*((p>>1)&1) + 2*(p>>3) + (p&1)
__device__ __forceinline__ int p32inv(int p) {
    return 16 * ((p >> 2) & 1) + 8 * ((p >> 1) & 1) + 2 * (p >> 3) + (p & 1);
}
__device__ __forceinline__ void cp_async16(void* s, const void* g) {
    unsigned a = (unsigned)__cvta_generic_to_shared(s);
    asm volatile("cp.async.cg.shared.global [%0], [%1], 16;\n" :: "r"(a), "l"(g) : "memory");
}
__device__ __forceinline__ void cp_commit() {
    asm volatile("cp.async.commit_group;\n" ::: "memory");
}
__device__ __forceinline__ void mma_f16(float c[4], uint32_t a0, uint32_t a1,
                                        uint32_t a2, uint32_t a3,
                                        uint32_t b0, uint32_t b1) {
    asm volatile(
        "mma.sync.aligned.m16n8k16.row.col.f32.f16.f16.f32 "
        "{%0,%1,%2,%3}, {%4,%5,%6,%7}, {%8,%9}, {%0,%1,%2,%3};\n"
        : "+f"(c[0]), "+f"(c[1]), "+f"(c[2]), "+f"(c[3])
        : "r"(a0), "r"(a1), "r"(a2), "r"(a3), "r"(b0), "r"(b1));
}

// ---------------- 1) LayerNorm -> Y (fp16, k-permuted cols) ----------------
__global__ void __launch_bounds__(256)
ln_kernel(const float* __restrict__ x, const float* __restrict__ gamma,
          const float* __restrict__ beta, __half* __restrict__ y)
{
    __shared__ float red1[8], red2[8];
    const int row = blockIdx.x, t = threadIdx.x;
    const int lane = t & 31, w = t >> 5;

    const float4* xr = (const float4*)(x + (size_t)row * H_DIM);
    float4 v0 = xr[t], v1 = xr[t + 256];
    float s = v0.x + v0.y + v0.z + v0.w + v1.x + v1.y + v1.z + v1.w;
    #pragma unroll
    for (int o = 16; o > 0; o >>= 1) s += __shfl_xor_sync(0xffffffffu, s, o);
    if (lane == 0) red1[w] = s;
    __syncthreads();
    float tot = 0.f;
    #pragma unroll
    for (int i = 0; i < 8; i++) tot += red1[i];
    const float mu = tot * (1.0f / H_DIM);

    float d[8] = {v0.x - mu, v0.y - mu, v0.z - mu, v0.w - mu,
                  v1.x - mu, v1.y - mu, v1.z - mu, v1.w - mu};
    float ss = 0.f;
    #pragma unroll
    for (int i = 0; i < 8; i++) ss += d[i] * d[i];
    #pragma unroll
    for (int o = 16; o > 0; o >>= 1) ss += __shfl_xor_sync(0xffffffffu, ss, o);
    if (lane == 0) red2[w] = ss;
    __syncthreads();
    float tot2 = 0.f;
    #pragma unroll
    for (int i = 0; i < 8; i++) tot2 += red2[i];
    const float rstd = rsqrtf(tot2 * (1.0f / H_DIM) + LN_EPS);

    const float4* g4 = (const float4*)gamma;
    const float4* b4 = (const float4*)beta;
    __half* yr = y + (size_t)row * H_DIM;

    #pragma unroll
    for (int half_ = 0; half_ < 2; half_++) {
        const int tt = t + half_ * 256;              // handles k = 4*tt .. 4*tt+3
        float4 ga = g4[tt], ba = b4[tt];
        const float* dd = d + half_ * 4;
        __half h0 = __float2half_rn(dd[0] * rstd * ga.x + ba.x);
        __half h1 = __float2half_rn(dd[1] * rstd * ga.y + ba.y);
        __half h2 = __float2half_rn(dd[2] * rstd * ga.z + ba.z);
        __half h3 = __float2half_rn(dd[3] * rstd * ga.w + ba.w);
        // p32 of k=4tt+j: base = 32*(tt>>3); off = 16*(tt&1)+2*((tt>>1)&1)+4*((tt>>2)&1)
        // j=0,1 -> base+off,+1 ; j=2,3 -> base+off+8,+9  (pairs contiguous)
        const int base = 32 * (tt >> 3);
        const int off  = 16 * (tt & 1) + 2 * ((tt >> 1) & 1) + 4 * ((tt >> 2) & 1);
        *(__half2*)(yr + base + off)     = __halves2half2(h0, h1);
        *(__half2*)(yr + base + off + 8) = __halves2half2(h2, h3);
    }
}

// ---------------- 2) transpose + fp16 + k-perm -----------------------------
// out[c][by + tx] = fp16(in[by + p32inv(tx)][bx + row])  -> storage[p32(k)] = val(k)
__global__ void __launch_bounds__(256)
transpose_h(const float* __restrict__ in, __half* __restrict__ out, int R, int C)
{
    __shared__ float t[32][33];
    const int bx = blockIdx.x * 32, by = blockIdx.y * 32;
    const int tx = threadIdx.x & 31, ty = threadIdx.x >> 5;
    #pragma unroll
    for (int j = 0; j < 4; j++)
        t[ty + j * 8][tx] = in[(size_t)(by + ty + j * 8) * C + bx + tx];
    __syncthreads();
    const int src = p32inv(tx);
    #pragma unroll
    for (int j = 0; j < 4; j++)
        out[(size_t)(bx + ty + j * 8) * R + by + tx] = __float2half_rn(t[src][ty + j * 8]);
}

// ---------------- 3) fp16 mma.sync GEMM (m16n8k16) -------------------------
// A [M,K], Bt [N,K] both fp16 row-major with p32 k-perm. CTA 128x128(BN),
// BK=32, 8 warps (4m x 2n), warp tile 32x64, double-buffered cp.async.
// Smem tile: 128 rows x 32 halves (64B rows) -> frag reads are contiguous
// 128B per quarter-warp: conflict-free with NO swizzle.
// G=1: B rows = 64 gelu + 64 linear; epilogue Z = fp16(gelu(Dg)*Dl), k-perm.
#define TBUF (128 * 32)                       // halves per tile buffer
#define GEMM_SMEM (4 * TBUF * 2)              // 32768 B

template<int G>
__global__ void __launch_bounds__(256, 2)
gemm_h(const __half* __restrict__ A, const __half* __restrict__ Bt,
       void* __restrict__ Cv, int K, int ldc)
{
    extern __shared__ __half sh[];
    __half* As = sh;
    __half* Bs = sh + 2 * TBUF;

    const int tid  = threadIdx.x;
    const int lane = tid & 31, wid = tid >> 5;
    const int q = lane >> 2, c = lane & 3;
    const int wm = wid & 3, wn = wid >> 2;

    // m-supertile swizzle (groups of 8 m-tiles) for B-slab L2 reuse
    const int lin = blockIdx.y * gridDim.x + blockIdx.x;
    const int mt_ = (lin / (8 * gridDim.x)) * 8 + (lin % 8);
    const int nt_ = (lin % (8 * gridDim.x)) / 8;
    const int m0  = mt_ * 128;
    const int n0  = nt_ * (G ? 64 : 128);

    float acc[2][8][4];
    #pragma unroll
    for (int i = 0; i < 2; i++)
        #pragma unroll
        for (int j = 0; j < 8; j++)
            #pragma unroll
            for (int p = 0; p < 4; p++) acc[i][j][p] = 0.f;

    const int NK = K >> 5;

    // Per-thread cp.async endpoints: 2 A units + 2 B units (16B each).
    const int ia0 = tid, ia1 = tid + 256;
    const int ra0 = ia0 >> 2, ua0 = ia0 & 3;
    const int ra1 = ia1 >> 2, ua1 = ia1 & 3;
    int bw0, bw1;
    if (G) { bw0 = (ra0 < 64) ? (n0 + ra0) : (I_DIM + n0 + ra0 - 64);
             bw1 = (ra1 < 64) ? (n0 + ra1) : (I_DIM + n0 + ra1 - 64); }
    else   { bw0 = n0 + ra0; bw1 = n0 + ra1; }
    const __half* apA0 = A  + (size_t)(m0 + ra0) * K + ua0 * 8;
    const __half* apA1 = A  + (size_t)(m0 + ra1) * K + ua1 * 8;
    const __half* apB0 = Bt + (size_t)bw0 * K + ua0 * 8;
    const __half* apB1 = Bt + (size_t)bw1 * K + ua1 * 8;
    const int dA0 = ra0 * 32 + ua0 * 8, dA1 = ra1 * 32 + ua1 * 8;

    auto load_tiles = [&](int buf) {
        __half* as = As + buf * TBUF;
        __half* bs = Bs + buf * TBUF;
        cp_async16(as + dA0, apA0);  cp_async16(as + dA1, apA1);
        cp_async16(bs + dA0, apB0);  cp_async16(bs + dA1, apB1);
        apA0 += 32; apA1 += 32; apB0 += 32; apB1 += 32;
    };

    load_tiles(0);
    cp_commit();

    for (int kt = 0; kt < NK; ++kt) {
        if (kt + 1 < NK) load_tiles((kt + 1) & 1);
        cp_commit();
        asm volatile("cp.async.wait_group 1;\n" ::: "memory");
        __syncthreads();

        const __half* as = As + (kt & 1) * TBUF;
        const __half* bs = Bs + (kt & 1) * TBUF;

        // A frags: one LDS.128 per (m-frag, row-half) covers BOTH k16 steps.
        // lo = {s0a0, s0a2, s1a0, s1a2}; hi = {s0a1, s0a3, s1a1, s1a3}
        uint4 alo[2], ahi[2];
        #pragma unroll
        for (int mt = 0; mt < 2; ++mt) {
            alo[mt] = *(const uint4*)(as + (wm * 32 + mt * 16 + q)     * 32 + 8 * c);
            ahi[mt] = *(const uint4*)(as + (wm * 32 + mt * 16 + 8 + q) * 32 + 8 * c);
        }
        #pragma unroll
        for (int ug = 0; ug < 2; ++ug) {      // B slots in chunks of 4
            uint4 bb[4];
            #pragma unroll
            for (int j = 0; j < 4; ++j) {
                const int u = ug * 4 + j;
                int brow;
                if (G) brow = (u >> 2) * 64 + wn * 32 + (u & 3) * 8 + q;
                else   brow = wn * 64 + u * 8 + q;
                bb[j] = *(const uint4*)(bs + brow * 32 + 8 * c);   // {s0b0,s0b1,s1b0,s1b1}
            }
            #pragma unroll
            for (int mt = 0; mt < 2; ++mt)
                #pragma unroll
                for (int j = 0; j < 4; ++j) {
                    const int u = ug * 4 + j;
                    mma_f16(acc[mt][u], alo[mt].x, ahi[mt].x, alo[mt].y, ahi[mt].y,
                            bb[j].x, bb[j].y);                     // k16 step 0
                    mma_f16(acc[mt][u], alo[mt].z, ahi[mt].z, alo[mt].w, ahi[mt].w,
                            bb[j].z, bb[j].w);                     // k16 step 1
                }
        }
        __syncthreads();
    }

    if (G) {
        // GeGLU epilogue: slots 0..3 gelu, 4..7 linear. Z cols k-permuted
        // (they are GEMM2's K dim); p32 of (even,odd) pair is contiguous.
        __half* Z = (__half*)Cv;
        #pragma unroll
        for (int mt = 0; mt < 2; ++mt)
            #pragma unroll
            for (int nt = 0; nt < 4; ++nt)
                #pragma unroll
                for (int rr = 0; rr < 2; ++rr) {
                    const int row = m0 + wm * 32 + mt * 16 + rr * 8 + q;
                    const int ic0 = n0 + wn * 32 + nt * 8 + 2 * c;
                    const float z0 = gelu_tanh(acc[mt][nt][rr * 2 + 0]) *
                                     acc[mt][4 + nt][rr * 2 + 0];
                    const float z1 = gelu_tanh(acc[mt][nt][rr * 2 + 1]) *
                                     acc[mt][4 + nt][rr * 2 + 1];
                    __half* zr = Z + (size_t)row * ldc;
                    *(__half2*)(zr + (ic0 & ~31) + p32(ic0 & 31)) =
                        __halves2half2(__float2half_rn(z0), __float2half_rn(z1));
                }
    } else {
        float* C = (float*)Cv;
        #pragma unroll
        for (int mt = 0; mt < 2; ++mt) {
            const int r = m0 + wm * 32 + mt * 16 + q;
            #pragma unroll
            for (int u = 0; u < 8; ++u) {
                const int cc = n0 + wn * 64 + u * 8 + 2 * c;
                *(float2*)(C + (size_t)r * ldc + cc)       = make_float2(acc[mt][u][0], acc[mt][u][1]);
                *(float2*)(C + (size_t)(r + 8) * ldc + cc) = make_float2(acc[mt][u][2], acc[mt][u][3]);
            }
        }
    }
}

// ---------------- launch ---------------------------------------------------
extern "C" void kernel_launch(void* const* d_in, const int* in_sizes, int n_in,
                              void* d_out, int out_size)
{
    (void)in_sizes; (void)n_in; (void)out_size;
    const float* x     = (const float*)d_in[0];
    const float* gamma = (const float*)d_in[1];
    const float* beta  = (const float*)d_in[2];
    const float* k1    = (const float*)d_in[3];
    const float* k2    = (const float*)d_in[4];
    float* out = (float*)d_out;

    __half *Y, *W1T, *W2T, *Z;
    cudaGetSymbolAddress((void**)&Y,   g_Y);
    cudaGetSymbolAddress((void**)&W1T, g_W1T);
    cudaGetSymbolAddress((void**)&W2T, g_W2T);
    cudaGetSymbolAddress((void**)&Z,   g_Z);

    cudaFuncSetAttribute(gemm_h<1>, cudaFuncAttributeMaxDynamicSharedMemorySize, GEMM_SMEM);
    cudaFuncSetAttribute(gemm_h<0>, cudaFuncAttributeMaxDynamicSharedMemorySize, GEMM_SMEM);

    // 1) LayerNorm -> Y (fp16, k-perm)
    ln_kernel<<<M_TOK, 256>>>(x, gamma, beta, Y);

    // 2) W1 [2048,16384] -> W1T [16384,2048];  W2 [8192,2048] -> W2T [2048,8192]
    transpose_h<<<dim3(16384 / 32, 2048 / 32), 256>>>(k1, W1T, 2048, 16384);
    transpose_h<<<dim3(2048 / 32, 8192 / 32), 256>>>(k2, W2T, 8192, 2048);

    // 3) GEMM1 + fused GeGLU -> Z   (n-tiles = I/64 = 128, m-tiles = 64)
    gemm_h<1><<<dim3(I_DIM / 64, M_TOK / 128), 256, GEMM_SMEM>>>(Y, W1T, Z, H_DIM, I_DIM);

    // 4) GEMM2 -> out              (n-tiles = H/128 = 16, m-tiles = 64)
    gemm_h<0><<<dim3(H_DIM / 128, M_TOK / 128), 256, GEMM_SMEM>>>(Z, W2T, out, I_DIM, H_DIM);
}

// round 13
// speedup vs baseline: 2.3982x; 1.0653x over previous
#include <cuda_runtime.h>
#include <cuda_fp16.h>
#include <cstdint>

// Fixed dims: B=4, S=2048 -> M=8192, H=2048, I=8192
#define M_TOK 8192
#define H_DIM 2048
#define I_DIM 8192
#define LN_EPS 1e-6f

// ---------------- scratch (device globals; no allocs) ----------------------
__device__ __half g_Y  [(size_t)M_TOK * H_DIM];       //  33 MB LN out (fp16, k-perm)
__device__ __half g_W1T[(size_t)2 * I_DIM * H_DIM];   //  67 MB W1^T [16384,2048] (k-perm)
__device__ __half g_W2T[(size_t)H_DIM * I_DIM];       //  33 MB W2^T [2048,8192]  (k-perm)
__device__ __half g_Z  [(size_t)M_TOK * I_DIM];       // 134 MB GeGLU out (fp16, k-perm)

// ---------------- helpers --------------------------------------------------
__device__ __forceinline__ float gelu_tanh(float v) {
    float u = 0.7978845608028654f * (v + 0.044715f * v * v * v);
    return 0.5f * v * (1.0f + tanhf(u));
}
// k-permutation within a 32-block; applied to BOTH operands -> result invariant.
__device__ __forceinline__ int p32(int k) {
    return 8 * ((k >> 1) & 3) + 4 * (k >> 4) + 2 * ((k >> 3) & 1) + (k & 1);
}
__device__ __forceinline__ int p32inv(int p) {
    return 16 * ((p >> 2) & 1) + 8 * ((p >> 1) & 1) + 2 * (p >> 3) + (p & 1);
}
__device__ __forceinline__ void cp_async16(void* s, const void* g) {
    unsigned a = (unsigned)__cvta_generic_to_shared(s);
    asm volatile("cp.async.cg.shared.global [%0], [%1], 16;\n" :: "r"(a), "l"(g) : "memory");
}
__device__ __forceinline__ void cp_commit() {
    asm volatile("cp.async.commit_group;\n" ::: "memory");
}
__device__ __forceinline__ void mma_f16(float c[4], uint32_t a0, uint32_t a1,
                                        uint32_t a2, uint32_t a3,
                                        uint32_t b0, uint32_t b1) {
    asm volatile(
        "mma.sync.aligned.m16n8k16.row.col.f32.f16.f16.f32 "
        "{%0,%1,%2,%3}, {%4,%5,%6,%7}, {%8,%9}, {%0,%1,%2,%3};\n"
        : "+f"(c[0]), "+f"(c[1]), "+f"(c[2]), "+f"(c[3])
        : "r"(a0), "r"(a1), "r"(a2), "r"(a3), "r"(b0), "r"(b1));
}

// ---------------- 1) LayerNorm -> Y (fp16, k-permuted cols) ----------------
__global__ void __launch_bounds__(256)
ln_kernel(const float* __restrict__ x, const float* __restrict__ gamma,
          const float* __restrict__ beta, __half* __restrict__ y)
{
    __shared__ float red1[8], red2[8];
    const int row = blockIdx.x, t = threadIdx.x;
    const int lane = t & 31, w = t >> 5;

    const float4* xr = (const float4*)(x + (size_t)row * H_DIM);
    float4 v0 = xr[t], v1 = xr[t + 256];
    float s = v0.x + v0.y + v0.z + v0.w + v1.x + v1.y + v1.z + v1.w;
    #pragma unroll
    for (int o = 16; o > 0; o >>= 1) s += __shfl_xor_sync(0xffffffffu, s, o);
    if (lane == 0) red1[w] = s;
    __syncthreads();
    float tot = 0.f;
    #pragma unroll
    for (int i = 0; i < 8; i++) tot += red1[i];
    const float mu = tot * (1.0f / H_DIM);

    float d[8] = {v0.x - mu, v0.y - mu, v0.z - mu, v0.w - mu,
                  v1.x - mu, v1.y - mu, v1.z - mu, v1.w - mu};
    float ss = 0.f;
    #pragma unroll
    for (int i = 0; i < 8; i++) ss += d[i] * d[i];
    #pragma unroll
    for (int o = 16; o > 0; o >>= 1) ss += __shfl_xor_sync(0xffffffffu, ss, o);
    if (lane == 0) red2[w] = ss;
    __syncthreads();
    float tot2 = 0.f;
    #pragma unroll
    for (int i = 0; i < 8; i++) tot2 += red2[i];
    const float rstd = rsqrtf(tot2 * (1.0f / H_DIM) + LN_EPS);

    const float4* g4 = (const float4*)gamma;
    const float4* b4 = (const float4*)beta;
    __half* yr = y + (size_t)row * H_DIM;

    #pragma unroll
    for (int half_ = 0; half_ < 2; half_++) {
        const int tt = t + half_ * 256;
        float4 ga = g4[tt], ba = b4[tt];
        const float* dd = d + half_ * 4;
        __half h0 = __float2half_rn(dd[0] * rstd * ga.x + ba.x);
        __half h1 = __float2half_rn(dd[1] * rstd * ga.y + ba.y);
        __half h2 = __float2half_rn(dd[2] * rstd * ga.z + ba.z);
        __half h3 = __float2half_rn(dd[3] * rstd * ga.w + ba.w);
        const int base = 32 * (tt >> 3);
        const int off  = 16 * (tt & 1) + 2 * ((tt >> 1) & 1) + 4 * ((tt >> 2) & 1);
        *(__half2*)(yr + base + off)     = __halves2half2(h0, h1);
        *(__half2*)(yr + base + off + 8) = __halves2half2(h2, h3);
    }
}

// ---------------- 2) transpose + fp16 + k-perm -----------------------------
__global__ void __launch_bounds__(256)
transpose_h(const float* __restrict__ in, __half* __restrict__ out, int R, int C)
{
    __shared__ float t[32][33];
    const int bx = blockIdx.x * 32, by = blockIdx.y * 32;
    const int tx = threadIdx.x & 31, ty = threadIdx.x >> 5;
    #pragma unroll
    for (int j = 0; j < 4; j++)
        t[ty + j * 8][tx] = in[(size_t)(by + ty + j * 8) * C + bx + tx];
    __syncthreads();
    const int src = p32inv(tx);
    #pragma unroll
    for (int j = 0; j < 4; j++)
        out[(size_t)(bx + ty + j * 8) * R + by + tx] = __float2half_rn(t[src][ty + j * 8]);
}

// ---------------- 3) fp16 mma.sync GEMM, 64x64 warp tile, 4-stage ----------
// A [M,K], Bt [N,K] fp16 row-major, p32 k-perm. CTA 128x128, 4 warps (2m x 2n),
// warp 64x64, BK=32, 4-stage cp.async, ONE __syncthreads per iter.
// Smem rows = 32 halves (64B), write swizzle: unit u stored at u^(row&3);
// frag reads use the matching per-thread constant offset -> all conflict-free.
// G=1: B rows = 64 gelu + 64 linear; epilogue Z = fp16(gelu(Dg)*Dl), k-perm.
#define TILEH (128 * 32)                 // halves per operand tile (8 KB)
#define STG_H (2 * TILEH)                // A+B per stage
#define STAGES 4
#define GEMM_SMEM (STAGES * STG_H * 2)   // 65536 B

template<int G>
__global__ void __launch_bounds__(128, 2)
gemm_h(const __half* __restrict__ A, const __half* __restrict__ Bt,
       void* __restrict__ Cv, int K, int ldc)
{
    extern __shared__ __half sh[];
    const int tid  = threadIdx.x;
    const int lane = tid & 31, wid = tid >> 5;
    const int q = lane >> 2, c = lane & 3;
    const int wm = wid >> 1, wn = wid & 1;

    // m-supertile swizzle (groups of 8 m-tiles) for B-slab L2 reuse
    const int lin = blockIdx.y * gridDim.x + blockIdx.x;
    const int mt_ = (lin / (8 * gridDim.x)) * 8 + (lin % 8);
    const int nt_ = (lin % (8 * gridDim.x)) / 8;
    const int m0  = mt_ * 128;
    const int n0  = nt_ * (G ? 64 : 128);

    float acc[4][8][4];
    #pragma unroll
    for (int i = 0; i < 4; i++)
        #pragma unroll
        for (int j = 0; j < 8; j++)
            #pragma unroll
            for (int p = 0; p < 4; p++) acc[i][j][p] = 0.f;

    const int NK = K >> 5;

    // cp.async mapping: thread t handles rows (t>>2)+32j, global k-unit (t&3).
    const int rA = tid >> 2, uu = tid & 3;
    const int su = uu ^ (rA & 3);                 // swizzled stored unit
    const __half* pa[4];
    const __half* pb[4];
    int dst[4];
    #pragma unroll
    for (int j = 0; j < 4; j++) {
        const int row = rA + 32 * j;
        pa[j] = A + (size_t)(m0 + row) * K + uu * 8;
        int brow;
        if (G) brow = (row < 64) ? (n0 + row) : (I_DIM + n0 + row - 64);
        else   brow = n0 + row;
        pb[j] = Bt + (size_t)brow * K + uu * 8;
        dst[j] = row * 32 + su * 8;
    }

    auto load_stage = [&](int s) {
        __half* as = sh + s * STG_H;
        __half* bs = as + TILEH;
        #pragma unroll
        for (int j = 0; j < 4; j++) {
            cp_async16(as + dst[j], pa[j]);
            cp_async16(bs + dst[j], pb[j]);
            pa[j] += 32; pb[j] += 32;
        }
    };

    // prologue: stages 0..2
    load_stage(0); cp_commit();
    load_stage(1); cp_commit();
    load_stage(2); cp_commit();

    const int cba = (c ^ (q & 3)) * 8;            // per-thread frag unit offset
    const int wmb = wm * 64, wnb = wn * (G ? 32 : 64);

    for (int kt = 0; kt < NK; ++kt) {
        if (kt <= NK - 3)
            asm volatile("cp.async.wait_group 2;\n" ::: "memory");
        else if (kt == NK - 2)
            asm volatile("cp.async.wait_group 1;\n" ::: "memory");
        else
            asm volatile("cp.async.wait_group 0;\n" ::: "memory");
        __syncthreads();
        if (kt + 3 < NK) { load_stage((kt + 3) & 3); cp_commit(); }

        const __half* as = sh + (kt & 3) * STG_H;
        const __half* bs = as + TILEH;

        // A frags: 4 m16-frags x 2 row-halves; each uint4 covers both k16 steps.
        uint4 alo[4], ahi[4];
        #pragma unroll
        for (int mf = 0; mf < 4; ++mf) {
            alo[mf] = *(const uint4*)(as + (wmb + mf * 16 + q)     * 32 + cba);
            ahi[mf] = *(const uint4*)(as + (wmb + mf * 16 + 8 + q) * 32 + cba);
        }
        #pragma unroll
        for (int ug = 0; ug < 2; ++ug) {
            uint4 bb[4];
            #pragma unroll
            for (int j = 0; j < 4; ++j) {
                const int u = ug * 4 + j;
                int brow;
                if (G) brow = (u >> 2) * 64 + wnb + (u & 3) * 8 + q;
                else   brow = wnb + u * 8 + q;
                bb[j] = *(const uint4*)(bs + brow * 32 + cba);
            }
            #pragma unroll
            for (int mf = 0; mf < 4; ++mf)
                #pragma unroll
                for (int j = 0; j < 4; ++j) {
                    const int u = ug * 4 + j;
                    mma_f16(acc[mf][u], alo[mf].x, ahi[mf].x, alo[mf].y, ahi[mf].y,
                            bb[j].x, bb[j].y);
                    mma_f16(acc[mf][u], alo[mf].z, ahi[mf].z, alo[mf].w, ahi[mf].w,
                            bb[j].z, bb[j].w);
                }
        }
    }

    if (G) {
        // slots 0..3 = gelu branch, 4..7 = linear branch (same I-cols).
        __half* Z = (__half*)Cv;
        #pragma unroll
        for (int mf = 0; mf < 4; ++mf)
            #pragma unroll
            for (int u = 0; u < 4; ++u)
                #pragma unroll
                for (int rr = 0; rr < 2; ++rr) {
                    const int row = m0 + wm * 64 + mf * 16 + rr * 8 + q;
                    const int ic0 = n0 + wn * 32 + u * 8 + 2 * c;
                    const float z0 = gelu_tanh(acc[mf][u][rr * 2 + 0]) *
                                     acc[mf][4 + u][rr * 2 + 0];
                    const float z1 = gelu_tanh(acc[mf][u][rr * 2 + 1]) *
                                     acc[mf][4 + u][rr * 2 + 1];
                    __half* zr = Z + (size_t)row * ldc;
                    *(__half2*)(zr + (ic0 & ~31) + p32(ic0 & 31)) =
                        __halves2half2(__float2half_rn(z0), __float2half_rn(z1));
                }
    } else {
        float* C = (float*)Cv;
        #pragma unroll
        for (int mf = 0; mf < 4; ++mf) {
            const int r = m0 + wm * 64 + mf * 16 + q;
            #pragma unroll
            for (int u = 0; u < 8; ++u) {
                const int cc = n0 + wn * 64 + u * 8 + 2 * c;
                *(float2*)(C + (size_t)r * ldc + cc)       = make_float2(acc[mf][u][0], acc[mf][u][1]);
                *(float2*)(C + (size_t)(r + 8) * ldc + cc) = make_float2(acc[mf][u][2], acc[mf][u][3]);
            }
        }
    }
}

// ---------------- launch ---------------------------------------------------
extern "C" void kernel_launch(void* const* d_in, const int* in_sizes, int n_in,
                              void* d_out, int out_size)
{
    (void)in_sizes; (void)n_in; (void)out_size;
    const float* x     = (const float*)d_in[0];
    const float* gamma = (const float*)d_in[1];
    const float* beta  = (const float*)d_in[2];
    const float* k1    = (const float*)d_in[3];
    const float* k2    = (const float*)d_in[4];
    float* out = (float*)d_out;

    __half *Y, *W1T, *W2T, *Z;
    cudaGetSymbolAddress((void**)&Y,   g_Y);
    cudaGetSymbolAddress((void**)&W1T, g_W1T);
    cudaGetSymbolAddress((void**)&W2T, g_W2T);
    cudaGetSymbolAddress((void**)&Z,   g_Z);

    cudaFuncSetAttribute(gemm_h<1>, cudaFuncAttributeMaxDynamicSharedMemorySize, GEMM_SMEM);
    cudaFuncSetAttribute(gemm_h<0>, cudaFuncAttributeMaxDynamicSharedMemorySize, GEMM_SMEM);

    // 1) LayerNorm -> Y (fp16, k-perm)
    ln_kernel<<<M_TOK, 256>>>(x, gamma, beta, Y);

    // 2) W1 [2048,16384] -> W1T [16384,2048];  W2 [8192,2048] -> W2T [2048,8192]
    transpose_h<<<dim3(16384 / 32, 2048 / 32), 256>>>(k1, W1T, 2048, 16384);
    transpose_h<<<dim3(2048 / 32, 8192 / 32), 256>>>(k2, W2T, 8192, 2048);

    // 3) GEMM1 + fused GeGLU -> Z   (n-tiles = I/64 = 128, m-tiles = 64)
    gemm_h<1><<<dim3(I_DIM / 64, M_TOK / 128), 128, GEMM_SMEM>>>(Y, W1T, Z, H_DIM, I_DIM);

    // 4) GEMM2 -> out              (n-tiles = H/128 = 16, m-tiles = 64)
    gemm_h<0><<<dim3(H_DIM / 128, M_TOK / 128), 128, GEMM_SMEM>>>(Z, W2T, out, I_DIM, H_DIM);
}